// round 11
// baseline (speedup 1.0000x reference)
#include <cuda_runtime.h>

// FWHT, DIM=4096, fp32, scale 1/64. Three in-register H16 passes over bit
// groups {b0,b1,b10,b11} / {b2..b5} / {b6..b9}, two smem exchanges.
// One CTA (256 thr) per row, 16 floats/thread.
//
// I/O fully coalesced: loads 4x LDG.128 lane-contiguous, stores 16x STG.32
// warp-contiguous (1 wavefront each).
//
// Smem: 4096 words (16 KB). GF(2) swizzle P(e) = e ^ (b6<<2) ^ (b10<<3) ^ (b11<<4)
// -> bank bits (b0, b1, b2^b6, b3^b10, b4^b11). Conflict-free in all phases:
//   W1  STS.128: 8-lane groups vary b2b3b4 -> distinct chunk banks
//   P2  scalar:  lanes vary b0,b1,b6,b10,b11 -> bank bijective
//   P3  scalar:  lanes vary b0..b4 -> bank bijective
//
// Pass-2 thread mapping (b6 = r&1, b0b1 = (r>>1)&3, b10b11 = (r>>3)&3,
// b7b8b9 = r>>5) makes exchange 1 warp-local: pass-2 warp R reads only data
// written by load-phase warp R -> __syncwarp() instead of __syncthreads().

#define FWHT_DIM 4096

__device__ __forceinline__ void h16(float (&v)[16]) {
#pragma unroll
    for (int h = 1; h < 16; h <<= 1) {
#pragma unroll
        for (int i = 0; i < 16; i++) {
            if (!(i & h)) {
                float a = v[i];
                float b = v[i + h];
                v[i]     = a + b;
                v[i + h] = a - b;
            }
        }
    }
}

__global__ __launch_bounds__(256, 7)
void fwht4096_kernel(const float* __restrict__ x, float* __restrict__ y) {
    __shared__ float s[4096];   // 16 KB, swizzled

    const int t = threadIdx.x;                    // 0..255
    const size_t row = (size_t)blockIdx.x * FWHT_DIM;

    float v[16];

    // ---- Load: lane-contiguous LDG.128. v[4j+c] = element (j<<10)|(t<<2)|c
    //      regs own {b0,b1,b10,b11}; lanes own b2..b9 (= t). ----
    {
        const float4* __restrict__ p = reinterpret_cast<const float4*>(x + row);
#pragma unroll
        for (int j = 0; j < 4; j++) {
            float4 f = __ldcs(p + t + 256 * j);
            v[4 * j + 0] = f.x;
            v[4 * j + 1] = f.y;
            v[4 * j + 2] = f.z;
            v[4 * j + 3] = f.w;
        }
    }

    h16(v);   // H16 over {b0,b1,b10,b11}

    // ---- W1: 4x STS.128. Chunk c = t + 256j; swizzled chunk flips
    //      c0^=c4 (b6), c1^=c8 (b10), c2^=c9 (b11). ----
    {
        float4* s4 = reinterpret_cast<float4*>(s);
        const int tb = t ^ ((t >> 4) & 1);          // fold b6 into chunk bit 0
#pragma unroll
        for (int j = 0; j < 4; j++) {
            int cj = (tb ^ ((j & 1) << 1) ^ ((j & 2) << 1)) + 256 * j;
            s4[cj] = make_float4(v[4 * j], v[4 * j + 1],
                                 v[4 * j + 2], v[4 * j + 3]);
        }
    }
    __syncwarp();   // exchange 1 is warp-local by construction

    // ---- Pass 2: thread r owns b6=r&1, b0b1=(r>>1)&3, b10b11=(r>>3)&3,
    //      b7b8b9=r>>5; regs m = b2..b5.
    //      addr = base + ((4m) ^ sw), sw = (b6<<2)|(b10<<3)|(b11<<4). ----
    {
        const int base = ((t >> 1) & 3) | ((t & 1) << 6) | ((t >> 5) << 7)
                       | (((t >> 3) & 3) << 10);
        const int sw = ((t & 1) << 2) | (((t >> 3) & 1) << 3)
                     | (((t >> 4) & 1) << 4);
#pragma unroll
        for (int m = 0; m < 16; m++)
            v[m] = s[base + ((4 * m) ^ sw)];

        h16(v);   // H16 over {b2..b5}

#pragma unroll
        for (int m = 0; m < 16; m++)
            s[base + ((4 * m) ^ sw)] = v[m];
    }
    __syncthreads();   // exchange 2 crosses the whole CTA

    // ---- Pass 3: thread w owns b0..b5 = w&63, b10b11 = w>>6; regs k = b6..b9.
    //      addr = ((basew ^ swf) + 64k) ^ ((k&1)<<2). ----
    {
        const int basew = (t & 63) | ((t >> 6) << 10);
        const int swf = (((t >> 6) & 1) << 3) | (((t >> 7) & 1) << 4);
        const int pb = basew ^ swf;
#pragma unroll
        for (int k = 0; k < 16; k++)
            v[k] = s[(pb + 64 * k) ^ ((k & 1) << 2)];

        h16(v);   // H16 over {b6..b9}

        const float sc = 0.015625f;   // 1/64 = 1/sqrt(4096)
        float* __restrict__ yr = y + row + basew;
#pragma unroll
        for (int k = 0; k < 16; k++)
            __stcs(yr + 64 * k, v[k] * sc);   // warp-contiguous, 1 wf each
    }
}

extern "C" void kernel_launch(void* const* d_in, const int* in_sizes, int n_in,
                              void* d_out, int out_size) {
    (void)n_in; (void)out_size;
    const float* x = (const float*)d_in[0];
    float* y = (float*)d_out;
    const int rows = in_sizes[0] / FWHT_DIM;   // 16384
    fwht4096_kernel<<<rows, 256>>>(x, y);
}

// round 12
// speedup vs baseline: 1.0016x; 1.0016x over previous
#include <cuda_runtime.h>

// FWHT, DIM=4096, fp32, scale 1/64. Three in-register H16 passes over bit
// groups {b0,b1,b10,b11} / {b2..b5} / {b6..b9}, two smem exchanges.
// One CTA (256 thr) per row, 16 floats/thread.
//
// I/O fully coalesced: loads 4x LDG.128 lane-contiguous, stores 16x STG.32
// warp-contiguous (1 wavefront each).
//
// Smem: 4096 words (16 KB). GF(2) swizzle P(e) = e ^ (b6<<2) ^ (b10<<3) ^ (b11<<4)
// -> bank bits (b0, b1, b2^b6, b3^b10, b4^b11). Conflict-free in all phases:
//   W1  STS.128: 8-lane groups vary b2b3b4 -> distinct chunk banks
//   P2  scalar:  lanes vary b0,b1,b6,b10,b11 -> bank bijective
//   P3  scalar:  lanes vary b0..b4 -> bank bijective
//
// Pass-2 thread mapping (b6 = r&1, b0b1 = (r>>1)&3, b10b11 = (r>>3)&3,
// b7b8b9 = r>>5) makes exchange 1 warp-local: pass-2 warp R reads only data
// written by load-phase warp R -> __syncwarp() instead of __syncthreads().

#define FWHT_DIM 4096

__device__ __forceinline__ void h16(float (&v)[16]) {
#pragma unroll
    for (int h = 1; h < 16; h <<= 1) {
#pragma unroll
        for (int i = 0; i < 16; i++) {
            if (!(i & h)) {
                float a = v[i];
                float b = v[i + h];
                v[i]     = a + b;
                v[i + h] = a - b;
            }
        }
    }
}

__global__ __launch_bounds__(256, 7)
void fwht4096_kernel(const float* __restrict__ x, float* __restrict__ y) {
    __shared__ float s[4096];   // 16 KB, swizzled

    const int t = threadIdx.x;                    // 0..255
    const size_t row = (size_t)blockIdx.x * FWHT_DIM;

    float v[16];

    // ---- Load: lane-contiguous LDG.128. v[4j+c] = element (j<<10)|(t<<2)|c
    //      regs own {b0,b1,b10,b11}; lanes own b2..b9 (= t). ----
    {
        const float4* __restrict__ p = reinterpret_cast<const float4*>(x + row);
#pragma unroll
        for (int j = 0; j < 4; j++) {
            float4 f = __ldcs(p + t + 256 * j);
            v[4 * j + 0] = f.x;
            v[4 * j + 1] = f.y;
            v[4 * j + 2] = f.z;
            v[4 * j + 3] = f.w;
        }
    }

    h16(v);   // H16 over {b0,b1,b10,b11}

    // ---- W1: 4x STS.128. Chunk c = t + 256j; swizzled chunk flips
    //      c0^=c4 (b6), c1^=c8 (b10), c2^=c9 (b11). ----
    {
        float4* s4 = reinterpret_cast<float4*>(s);
        const int tb = t ^ ((t >> 4) & 1);          // fold b6 into chunk bit 0
#pragma unroll
        for (int j = 0; j < 4; j++) {
            int cj = (tb ^ ((j & 1) << 1) ^ ((j & 2) << 1)) + 256 * j;
            s4[cj] = make_float4(v[4 * j], v[4 * j + 1],
                                 v[4 * j + 2], v[4 * j + 3]);
        }
    }
    __syncwarp();   // exchange 1 is warp-local by construction

    // ---- Pass 2: thread r owns b6=r&1, b0b1=(r>>1)&3, b10b11=(r>>3)&3,
    //      b7b8b9=r>>5; regs m = b2..b5.
    //      addr = base + ((4m) ^ sw), sw = (b6<<2)|(b10<<3)|(b11<<4). ----
    {
        const int base = ((t >> 1) & 3) | ((t & 1) << 6) | ((t >> 5) << 7)
                       | (((t >> 3) & 3) << 10);
        const int sw = ((t & 1) << 2) | (((t >> 3) & 1) << 3)
                     | (((t >> 4) & 1) << 4);
#pragma unroll
        for (int m = 0; m < 16; m++)
            v[m] = s[base + ((4 * m) ^ sw)];

        h16(v);   // H16 over {b2..b5}

#pragma unroll
        for (int m = 0; m < 16; m++)
            s[base + ((4 * m) ^ sw)] = v[m];
    }
    __syncthreads();   // exchange 2 crosses the whole CTA

    // ---- Pass 3: thread w owns b0..b5 = w&63, b10b11 = w>>6; regs k = b6..b9.
    //      addr = ((basew ^ swf) + 64k) ^ ((k&1)<<2). ----
    {
        const int basew = (t & 63) | ((t >> 6) << 10);
        const int swf = (((t >> 6) & 1) << 3) | (((t >> 7) & 1) << 4);
        const int pb = basew ^ swf;
#pragma unroll
        for (int k = 0; k < 16; k++)
            v[k] = s[(pb + 64 * k) ^ ((k & 1) << 2)];

        h16(v);   // H16 over {b6..b9}

        const float sc = 0.015625f;   // 1/64 = 1/sqrt(4096)
        float* __restrict__ yr = y + row + basew;
#pragma unroll
        for (int k = 0; k < 16; k++)
            __stcs(yr + 64 * k, v[k] * sc);   // warp-contiguous, 1 wf each
    }
}

extern "C" void kernel_launch(void* const* d_in, const int* in_sizes, int n_in,
                              void* d_out, int out_size) {
    (void)n_in; (void)out_size;
    const float* x = (const float*)d_in[0];
    float* y = (float*)d_out;
    const int rows = in_sizes[0] / FWHT_DIM;   // 16384
    fwht4096_kernel<<<rows, 256>>>(x, y);
}